// round 1
// baseline (speedup 1.0000x reference)
#include <cuda_runtime.h>

#define HID   128
#define BATCH 2048
#define ABUD  512
#define RPG   8      // rows per group
#define RPB   16     // rows per block (2 groups of 128 threads)
#define EMB   68
#define XCOLS 39

// scratch: per batch row [0..5]=cbar (mean-over-j coefficients), [6]=sbase, [7]=pad
__device__ float g_coef[BATCH * 8];

__global__ __launch_bounds__(256, 1) void mlp_kernel(
    const float* __restrict__ x,
    const float* __restrict__ emb_id, const float* __restrict__ emb_period,
    const float* __restrict__ emb_time,
    const float* __restrict__ Wf1, const float* __restrict__ bf1,
    const float* __restrict__ Wf2, const float* __restrict__ bf2,
    const float* __restrict__ Wc1, const float* __restrict__ bc1,
    const float* __restrict__ Wc2, const float* __restrict__ bc2,
    const float* __restrict__ Wb1, const float* __restrict__ bb1,
    const float* __restrict__ Wb2, const float* __restrict__ bb2)
{
    __shared__ float emb_s[RPB][EMB];
    __shared__ float hbuf[2][2][RPG][HID];   // [group][pingpong][row][unit]
    __shared__ float wc2bar[HID][8];         // mean-over-j of Wc2 rows (padded)
    __shared__ int   idx_s[RPB][3];

    const int tid  = threadIdx.x;
    const int g    = tid >> 7;      // group 0/1
    const int t    = tid & 127;    // hidden unit
    const int row0 = blockIdx.x * RPB;

    // categorical indices for this block's 16 rows
    if (tid < RPB * 3) {
        int r = tid / 3, c = tid % 3;
        idx_s[r][c] = (int)x[(row0 + r) * XCOLS + c];
    }
    // wc2bar[t][k] = (1/8) * sum_j Wc2[t, j*6+k]   (group 0 only)
    if (g == 0) {
        #pragma unroll
        for (int k = 0; k < 6; k++) {
            float s = 0.f;
            #pragma unroll
            for (int j = 0; j < 8; j++) s += Wc2[t * 48 + j * 6 + k];
            wc2bar[t][k] = s * 0.125f;
        }
    }
    __syncthreads();

    // build embeddings: [emb_id(8) | emb_period(8) | emb_time(16) | x[3:](36)]
    for (int idx = tid; idx < RPB * EMB; idx += 256) {
        int r = idx / EMB, c = idx % EMB;
        float v;
        if      (c < 8)  v = emb_id    [idx_s[r][1] * 8  + c];
        else if (c < 16) v = emb_period[idx_s[r][0] * 8  + (c - 8)];
        else if (c < 32) v = emb_time  [idx_s[r][2] * 16 + (c - 16)];
        else             v = x[(row0 + r) * XCOLS + 3 + (c - 32)];
        emb_s[r][c] = v;
    }
    __syncthreads();

    float acc[RPG];

    // stage 1: h1 = relu(emb @ Wf1 + bf1)  -> hbuf[g][0]
    {
        float b = bf1[t];
        #pragma unroll
        for (int r = 0; r < RPG; r++) acc[r] = b;
    }
    for (int i = 0; i < EMB; i++) {
        float w = Wf1[i * HID + t];
        #pragma unroll
        for (int r = 0; r < RPG; r++) acc[r] += emb_s[g * RPG + r][i] * w;
    }
    #pragma unroll
    for (int r = 0; r < RPG; r++) hbuf[g][0][r][t] = fmaxf(acc[r], 0.f);
    __syncthreads();

    // stage 2: h2 = relu(h1 @ Wf2 + bf2)  -> hbuf[g][1]
    {
        float b = bf2[t];
        #pragma unroll
        for (int r = 0; r < RPG; r++) acc[r] = b;
    }
    for (int i = 0; i < HID; i++) {
        float w = Wf2[i * HID + t];
        #pragma unroll
        for (int r = 0; r < RPG; r++) acc[r] += hbuf[g][0][r][i] * w;
    }
    #pragma unroll
    for (int r = 0; r < RPG; r++) hbuf[g][1][r][t] = fmaxf(acc[r], 0.f);
    __syncthreads();

    // hc = relu(h2 @ Wc1 + bc1)  -> hbuf[g][0]  (last read of [g][0] was before sync)
    {
        float b = bc1[t];
        #pragma unroll
        for (int r = 0; r < RPG; r++) acc[r] = b;
    }
    for (int i = 0; i < HID; i++) {
        float w = Wc1[i * HID + t];
        #pragma unroll
        for (int r = 0; r < RPG; r++) acc[r] += hbuf[g][1][r][i] * w;
    }
    #pragma unroll
    for (int r = 0; r < RPG; r++) hbuf[g][0][r][t] = fmaxf(acc[r], 0.f);

    // hb = relu(h2 @ Wb1 + bb1)  (keep in regs, h2 still lives in hbuf[g][1])
    float hb[RPG];
    {
        float b = bb1[t];
        #pragma unroll
        for (int r = 0; r < RPG; r++) hb[r] = b;
    }
    for (int i = 0; i < HID; i++) {
        float w = Wb1[i * HID + t];
        #pragma unroll
        for (int r = 0; r < RPG; r++) hb[r] += hbuf[g][1][r][i] * w;
    }
    __syncthreads();                      // everyone done reading hbuf[g][1]
    #pragma unroll
    for (int r = 0; r < RPG; r++) hbuf[g][1][r][t] = fmaxf(hb[r], 0.f);
    __syncthreads();

    // reductions: rb = row-in-block (0..15), slot 0..5 = cbar[k], 6 = sbase
    {
        int rb = tid >> 4;
        int slot = tid & 15;
        int gg = rb >> 3, rr = rb & 7;
        if (slot < 6) {
            float s = 0.f;
            for (int i = 0; i < HID; i++) s += hbuf[gg][0][rr][i] * wc2bar[i][slot];
            float bb = 0.f;
            #pragma unroll
            for (int j = 0; j < 8; j++) bb += bc2[j * 6 + slot];
            s += bb * 0.125f;
            g_coef[(row0 + rb) * 8 + slot] = s;
        } else if (slot == 6) {
            float s = 0.f;
            for (int i = 0; i < HID; i++) s += hbuf[gg][1][rr][i] * Wb2[i];
            s += bb2[0];
            g_coef[(row0 + rb) * 8 + 6] = s;
        } else if (slot == 7) {
            g_coef[(row0 + rb) * 8 + 7] = 0.f;
        }
    }
}

// out[b,a] = sbase[b] * ( silu(x) + sum_k Bk(x) * cbar[b,k] )
// uniform cubic B-spline, knots spacing h = 2/3, x in [-1, 1)
__global__ __launch_bounds__(256, 8) void budget_kernel(
    const float* __restrict__ budget, float* __restrict__ out)
{
    int gidx = blockIdx.x * blockDim.x + threadIdx.x;   // 0 .. 262143 (quads)
    int b = gidx >> 7;                                   // 128 quads per row

    float4 bv = ((const float4*)budget)[gidx];

    const float4* cp = (const float4*)(g_coef + b * 8);
    float4 c0 = cp[0], c1 = cp[1];
    float c[6] = {c0.x, c0.y, c0.z, c0.w, c1.x, c1.y};
    float sbase = c1.z;

    float xs[4] = {bv.x, bv.y, bv.z, bv.w};
    float o[4];
    #pragma unroll
    for (int e = 0; e < 4; e++) {
        float X = xs[e];
        float sil = X / (1.f + __expf(-X));
        float tpos = (X + 1.0f) * 1.5f;          // (x - t0)/h with t0=-1, h=2/3
        int m = (int)tpos;
        m = min(max(m, 0), 2);
        float u = tpos - (float)m;
        float u2 = u * u, u3 = u2 * u;
        const float k6 = 1.f / 6.f;
        float om = 1.f - u;
        float w0 = om * om * om * k6;
        float w1 = (3.f * u3 - 6.f * u2 + 4.f) * k6;
        float w2 = (-3.f * u3 + 3.f * u2 + 3.f * u + 1.f) * k6;
        float w3 = u3 * k6;
        float sp = w0 * c[m] + w1 * c[m + 1] + w2 * c[m + 2] + w3 * c[m + 3];
        o[e] = sbase * (sil + sp);
    }
    ((float4*)out)[gidx] = make_float4(o[0], o[1], o[2], o[3]);
}

extern "C" void kernel_launch(void* const* d_in, const int* in_sizes, int n_in,
                              void* d_out, int out_size)
{
    const float* x          = (const float*)d_in[0];
    const float* budget     = (const float*)d_in[1];
    const float* emb_id     = (const float*)d_in[2];
    const float* emb_period = (const float*)d_in[3];
    const float* emb_time   = (const float*)d_in[4];
    const float* Wf1 = (const float*)d_in[5];
    const float* bf1 = (const float*)d_in[6];
    const float* Wf2 = (const float*)d_in[7];
    const float* bf2 = (const float*)d_in[8];
    const float* Wc1 = (const float*)d_in[9];
    const float* bc1 = (const float*)d_in[10];
    const float* Wc2 = (const float*)d_in[11];
    const float* bc2 = (const float*)d_in[12];
    // d_in[13..16] = Ws1/bs1/Ws2/bs2 : computed-but-unused in reference, skipped
    const float* Wb1 = (const float*)d_in[17];
    const float* bb1 = (const float*)d_in[18];
    const float* Wb2 = (const float*)d_in[19];
    const float* bb2 = (const float*)d_in[20];

    float* out = (float*)d_out;

    mlp_kernel<<<BATCH / RPB, 256>>>(x, emb_id, emb_period, emb_time,
                                     Wf1, bf1, Wf2, bf2, Wc1, bc1, Wc2, bc2,
                                     Wb1, bb1, Wb2, bb2);
    budget_kernel<<<(BATCH * ABUD / 4) / 256, 256>>>(budget, out);
}

// round 2
// speedup vs baseline: 1.3418x; 1.3418x over previous
#include <cuda_runtime.h>

#define HID   128
#define BATCH 2048
#define ABUD  512
#define RPB   16      // batch rows per block
#define XCOLS 39

// dynamic shared layout (float offsets)
#define OFF_W     0        // Wsh [128][128]            16384 floats
#define OFF_H     16384    // hbuf [2 grp][3 buf][8][128] 12288
#define OFF_EMB   28672    // emb  [16][72]               1152
#define OFF_WC2   29824    // wc2bar [128][8]             1024
#define OFF_CBAR  30848    // cbar [16][8]                 128
#define OFF_CB    30976    // coefB [16][4 pad][4]         256
#define OFF_SB    31232    // sbase [16]                    16
#define SMEM_FLOATS 31248
#define SMEM_BYTES (SMEM_FLOATS * 4)

// C[8 rows][unit t] += A[8 rows][0..K) * W[0..K)[t], relu, K % 4 == 0
template<int K, int RS>
__device__ __forceinline__ void gemv8(const float* __restrict__ act,
                                      const float* __restrict__ W,
                                      float bias, float* __restrict__ outp, int t)
{
    float acc[8];
    #pragma unroll
    for (int r = 0; r < 8; r++) acc[r] = bias;
    #pragma unroll 2
    for (int k = 0; k < K; k += 4) {
        float w0 = W[(k + 0) * HID + t];
        float w1 = W[(k + 1) * HID + t];
        float w2 = W[(k + 2) * HID + t];
        float w3 = W[(k + 3) * HID + t];
        #pragma unroll
        for (int r = 0; r < 8; r++) {
            float4 a = *reinterpret_cast<const float4*>(act + r * RS + k);
            acc[r] = fmaf(a.x, w0, acc[r]);
            acc[r] = fmaf(a.y, w1, acc[r]);
            acc[r] = fmaf(a.z, w2, acc[r]);
            acc[r] = fmaf(a.w, w3, acc[r]);
        }
    }
    #pragma unroll
    for (int r = 0; r < 8; r++) outp[r * HID + t] = fmaxf(acc[r], 0.f);
}

__device__ __forceinline__ void stage128(const float* __restrict__ src, float* __restrict__ dst, int tid)
{
    const float4* s4 = (const float4*)src;
    float4* d4 = (float4*)dst;
    #pragma unroll
    for (int i = 0; i < 16; i++) d4[tid + i * 256] = s4[tid + i * 256];  // 128*32 = 4096 float4
}

__global__ __launch_bounds__(256, 1) void fused_kernel(
    const float* __restrict__ x,
    const float* __restrict__ budget,
    const float* __restrict__ emb_id, const float* __restrict__ emb_period,
    const float* __restrict__ emb_time,
    const float* __restrict__ Wf1, const float* __restrict__ bf1,
    const float* __restrict__ Wf2, const float* __restrict__ bf2,
    const float* __restrict__ Wc1, const float* __restrict__ bc1,
    const float* __restrict__ Wc2, const float* __restrict__ bc2,
    const float* __restrict__ Wb1, const float* __restrict__ bb1,
    const float* __restrict__ Wb2, const float* __restrict__ bb2,
    float* __restrict__ out)
{
    extern __shared__ float sm[];
    __shared__ int idx_s[RPB][3];

    const int tid  = threadIdx.x;
    const int g    = tid >> 7;     // row-group 0/1 (8 rows each)
    const int t    = tid & 127;    // hidden unit
    const int row0 = blockIdx.x * RPB;

    if (tid < RPB * 3) {
        int r = tid / 3, c = tid % 3;
        idx_s[r][c] = (int)x[(row0 + r) * XCOLS + c];
    }
    // wc2bar[i][k] = (1/8) sum_j Wc2[i, j*6+k]  (group 0; vectorized row read)
    if (g == 0) {
        float s[6] = {0, 0, 0, 0, 0, 0};
        const float4* w4 = (const float4*)(Wc2 + t * 48);
        #pragma unroll
        for (int v = 0; v < 12; v++) {
            float4 f = w4[v];
            s[(v * 4 + 0) % 6] += f.x;
            s[(v * 4 + 1) % 6] += f.y;
            s[(v * 4 + 2) % 6] += f.z;
            s[(v * 4 + 3) % 6] += f.w;
        }
        #pragma unroll
        for (int k = 0; k < 6; k++) sm[OFF_WC2 + t * 8 + k] = s[k] * 0.125f;
    }
    __syncthreads();

    // embeddings: [id 8 | period 8 | time 16 | feats 36 | pad 4] -> 72 cols
    for (int idx = tid; idx < RPB * 72; idx += 256) {
        int r = idx / 72, c = idx % 72;
        float v = 0.f;
        if      (c < 8)  v = emb_id    [idx_s[r][1] * 8  + c];
        else if (c < 16) v = emb_period[idx_s[r][0] * 8  + (c - 8)];
        else if (c < 32) v = emb_time  [idx_s[r][2] * 16 + (c - 16)];
        else if (c < 68) v = x[(row0 + r) * XCOLS + 3 + (c - 32)];
        sm[OFF_EMB + idx] = v;
    }
    __syncthreads();

    float* H = sm + OFF_H;
    #define HBUF(gg, p, rr) (H + (((gg) * 3 + (p)) * 8 + (rr)) * HID)

    // ---- layer f1: emb(72, padded) -> H[g][0] ----
    {
        const float4* s4 = (const float4*)Wf1;   // 68*128 floats = 2176 float4
        float4* d4 = (float4*)(sm + OFF_W);
        #pragma unroll
        for (int i = 0; i < 8; i++) d4[tid + i * 256] = s4[tid + i * 256];   // 2048
        if (tid < 128) d4[2048 + tid] = s4[2048 + tid];                       // 2176
        if (tid < 128) d4[2176 + tid] = make_float4(0.f, 0.f, 0.f, 0.f);      // zero rows 68..71
    }
    __syncthreads();
    gemv8<72, 72>(sm + OFF_EMB + g * 8 * 72, sm + OFF_W, bf1[t], HBUF(g, 0, 0), t);
    __syncthreads();

    // ---- layer f2: H[g][0] -> H[g][1] ----
    stage128(Wf2, sm + OFF_W, tid);
    __syncthreads();
    gemv8<128, 128>(HBUF(g, 0, 0), sm + OFF_W, bf2[t], HBUF(g, 1, 0), t);
    __syncthreads();

    // ---- layer c1: H[g][1] -> H[g][0] (hc) ----
    stage128(Wc1, sm + OFF_W, tid);
    __syncthreads();
    gemv8<128, 128>(HBUF(g, 1, 0), sm + OFF_W, bc1[t], HBUF(g, 0, 0), t);
    __syncthreads();

    // ---- layer b1: H[g][1] -> H[g][2] (hb2) ----
    stage128(Wb1, sm + OFF_W, tid);
    __syncthreads();
    gemv8<128, 128>(HBUF(g, 1, 0), sm + OFF_W, bb1[t], HBUF(g, 2, 0), t);
    __syncthreads();

    // ---- epilogue dots: cbar[16][6], sbase[16] ----
    {
        int rb = tid >> 4, slot = tid & 15;
        int gg = rb >> 3, rr = rb & 7;
        if (slot < 6) {
            const float* hc = HBUF(gg, 0, rr);
            float s = 0.f;
            for (int i = 0; i < HID; i++) s += hc[i] * sm[OFF_WC2 + i * 8 + slot];
            float bb = 0.f;
            #pragma unroll
            for (int j = 0; j < 8; j++) bb += bc2[j * 6 + slot];
            sm[OFF_CBAR + rb * 8 + slot] = s + bb * 0.125f;
        } else if (slot == 6) {
            const float* hb = HBUF(gg, 2, rr);
            float s = 0.f;
            for (int i = 0; i < HID; i++) s += hb[i] * Wb2[i];
            sm[OFF_SB + rb] = s + bb2[0];
        }
    }
    __syncthreads();

    // ---- per-row piecewise cubic in X: 3 segments x (B0..B3) ----
    if (tid < 48) {
        int rb = tid / 3, m = tid - rb * 3;
        const float* c = sm + OFF_CBAR + rb * 8 + m;
        float c0 = c[0], c1 = c[1], c2 = c[2], c3 = c[3];
        const float k6 = 1.f / 6.f;
        float A0 = (c0 + 4.f * c1 + c2) * k6;
        float A1 = (c2 - c0) * 0.5f;
        float A2 = (c0 - 2.f * c1 + c2) * 0.5f;
        float A3 = (c3 - c0 + 3.f * (c1 - c2)) * k6;
        float d  = 1.5f - (float)m;           // u = 1.5*X + d
        float B0 = A0 + d * (A1 + d * (A2 + d * A3));
        float B1 = 1.5f * (A1 + d * (2.f * A2 + 3.f * A3 * d));
        float B2 = 2.25f * (A2 + 3.f * A3 * d);
        float B3 = 3.375f * A3;
        ((float4*)(sm + OFF_CB))[rb * 4 + m] = make_float4(B0, B1, B2, B3);
    }
    __syncthreads();

    // ---- budget phase: 16 rows x 512 points = 2048 float4 ----
    const float4* bud4 = (const float4*)budget + row0 * 128;
    float4* out4 = (float4*)out + row0 * 128;
    const float4* cb4 = (const float4*)(sm + OFF_CB);
    #pragma unroll
    for (int it = 0; it < 8; it++) {
        int q = tid + it * 256;
        int row = q >> 7;
        float4 bv = bud4[q];
        float sb = sm[OFF_SB + row];
        float xs[4] = {bv.x, bv.y, bv.z, bv.w};
        float o[4];
        #pragma unroll
        for (int e = 0; e < 4; e++) {
            float X = xs[e];
            float tp = fmaf(X, 1.5f, 1.5f);
            int m = min((int)tp, 2);
            float4 B = cb4[row * 4 + m];
            float sp = fmaf(fmaf(fmaf(B.w, X, B.z), X, B.y), X, B.x);
            float sil = X / (1.f + __expf(-X));
            o[e] = sb * (sil + sp);
        }
        out4[q] = make_float4(o[0], o[1], o[2], o[3]);
    }
}

extern "C" void kernel_launch(void* const* d_in, const int* in_sizes, int n_in,
                              void* d_out, int out_size)
{
    const float* x          = (const float*)d_in[0];
    const float* budget     = (const float*)d_in[1];
    const float* emb_id     = (const float*)d_in[2];
    const float* emb_period = (const float*)d_in[3];
    const float* emb_time   = (const float*)d_in[4];
    const float* Wf1 = (const float*)d_in[5];
    const float* bf1 = (const float*)d_in[6];
    const float* Wf2 = (const float*)d_in[7];
    const float* bf2 = (const float*)d_in[8];
    const float* Wc1 = (const float*)d_in[9];
    const float* bc1 = (const float*)d_in[10];
    const float* Wc2 = (const float*)d_in[11];
    const float* bc2 = (const float*)d_in[12];
    // d_in[13..16] = Ws1/bs1/Ws2/bs2 : unused in reference output
    const float* Wb1 = (const float*)d_in[17];
    const float* bb1 = (const float*)d_in[18];
    const float* Wb2 = (const float*)d_in[19];
    const float* bb2 = (const float*)d_in[20];

    cudaFuncSetAttribute(fused_kernel, cudaFuncAttributeMaxDynamicSharedMemorySize, SMEM_BYTES);

    fused_kernel<<<BATCH / RPB, 256, SMEM_BYTES>>>(
        x, budget, emb_id, emb_period, emb_time,
        Wf1, bf1, Wf2, bf2, Wc1, bc1, Wc2, bc2,
        Wb1, bb1, Wb2, bb2, (float*)d_out);
}

// round 3
// speedup vs baseline: 1.5270x; 1.1380x over previous
#include <cuda_runtime.h>
#include <cstdint>

#define HID   128
#define BATCH 2048
#define RPB   16      // batch rows per block
#define XCOLS 39

// dynamic shared layout (float offsets)
#define OFF_W0    0        // weight buffer 0: [128][128]  16384
#define OFF_W1    16384    // weight buffer 1: [128][128]  16384
#define OFF_H     32768    // hbuf [2 grp][2 buf][8][128]   4096
#define OFF_EMB   36864    // emb  [16][72]                 1152
#define OFF_WC2   38016    // wc2bar [128][8]               1024
#define OFF_CBAR  39040    // cbar [16][8]                   128
#define OFF_CB    39168    // coefB [16][4 pad][4]           256
#define OFF_SB    39424    // sbase [16]                      16
#define OFF_RED   39440    // sbase partials [16 rows][4]     64
#define SMEM_FLOATS 39504
#define SMEM_BYTES (SMEM_FLOATS * 4)

__device__ __forceinline__ void cp16(uint32_t dst_smem, const void* src) {
    asm volatile("cp.async.cg.shared.global [%0], [%1], 16;\n" :: "r"(dst_smem), "l"(src));
}
#define CP_COMMIT() asm volatile("cp.async.commit_group;\n" ::: "memory")
#define CP_WAIT0()  asm volatile("cp.async.wait_group 0;\n" ::: "memory")

// stage a 128x128 float matrix (4096 float4) into smem via cp.async
__device__ __forceinline__ void stage_async(const float* __restrict__ src,
                                            uint32_t dst_smem_bytes, int tid)
{
    const float4* s4 = (const float4*)src;
    #pragma unroll
    for (int i = 0; i < 16; i++)
        cp16(dst_smem_bytes + (tid + i * 256) * 16, s4 + tid + i * 256);
}

// acc[r] += act[r][k] * W[k][t] over K (K%4==0); weights in smem, act in smem
template<int K, int RS>
__device__ __forceinline__ void gemv8_acc(const float* __restrict__ act,
                                          const float* __restrict__ W,
                                          float bias, float acc[8], int t)
{
    #pragma unroll
    for (int r = 0; r < 8; r++) acc[r] = bias;
    #pragma unroll 2
    for (int k = 0; k < K; k += 4) {
        float w0 = W[(k + 0) * HID + t];
        float w1 = W[(k + 1) * HID + t];
        float w2 = W[(k + 2) * HID + t];
        float w3 = W[(k + 3) * HID + t];
        #pragma unroll
        for (int r = 0; r < 8; r++) {
            float4 a = *reinterpret_cast<const float4*>(act + r * RS + k);
            acc[r] = fmaf(a.x, w0, acc[r]);
            acc[r] = fmaf(a.y, w1, acc[r]);
            acc[r] = fmaf(a.z, w2, acc[r]);
            acc[r] = fmaf(a.w, w3, acc[r]);
        }
    }
}

__global__ __launch_bounds__(256, 1) void fused_kernel(
    const float* __restrict__ x,
    const float* __restrict__ budget,
    const float* __restrict__ emb_id, const float* __restrict__ emb_period,
    const float* __restrict__ emb_time,
    const float* __restrict__ Wf1, const float* __restrict__ bf1,
    const float* __restrict__ Wf2, const float* __restrict__ bf2,
    const float* __restrict__ Wc1, const float* __restrict__ bc1,
    const float* __restrict__ Wc2, const float* __restrict__ bc2,
    const float* __restrict__ Wb1, const float* __restrict__ bb1,
    const float* __restrict__ Wb2, const float* __restrict__ bb2,
    float* __restrict__ out)
{
    extern __shared__ float sm[];
    __shared__ int idx_s[RPB][3];

    const int tid  = threadIdx.x;
    const int g    = tid >> 7;     // row-group 0/1 (8 rows each)
    const int t    = tid & 127;    // hidden unit
    const int row0 = blockIdx.x * RPB;
    const uint32_t smb = (uint32_t)__cvta_generic_to_shared(sm);

    // ---- kick off Wf1 staging (68 rows + 4 zero-pad rows = 72x128) ----
    {
        const float4* s4 = (const float4*)Wf1;   // 2176 float4
        #pragma unroll
        for (int i = 0; i < 8; i++)
            cp16(smb + (OFF_W0 * 4) + (tid + i * 256) * 16, s4 + tid + i * 256);
        if (tid < 128)
            cp16(smb + (OFF_W0 * 4) + (2048 + tid) * 16, s4 + 2048 + tid);
        CP_COMMIT();
        if (tid < 128)   // zero pad rows 68..71
            ((float4*)(sm + OFF_W0))[2176 + tid] = make_float4(0.f, 0.f, 0.f, 0.f);
    }

    if (tid < RPB * 3) {
        int r = tid / 3, c = tid % 3;
        idx_s[r][c] = (int)x[(row0 + r) * XCOLS + c];
    }
    // wc2bar[i][k] = (1/8) sum_j Wc2[i, j*6+k]  (group 0)
    if (g == 0) {
        float s[6] = {0, 0, 0, 0, 0, 0};
        const float4* w4 = (const float4*)(Wc2 + t * 48);
        #pragma unroll
        for (int v = 0; v < 12; v++) {
            float4 f = w4[v];
            s[(v * 4 + 0) % 6] += f.x;
            s[(v * 4 + 1) % 6] += f.y;
            s[(v * 4 + 2) % 6] += f.z;
            s[(v * 4 + 3) % 6] += f.w;
        }
        #pragma unroll
        for (int k = 0; k < 6; k++) sm[OFF_WC2 + t * 8 + k] = s[k] * 0.125f;
    }
    __syncthreads();   // idx_s ready

    // embeddings: [id 8 | period 8 | time 16 | feats 36 | pad 4] -> 72 cols
    for (int idx = tid; idx < RPB * 72; idx += 256) {
        int r = idx / 72, c = idx % 72;
        float v = 0.f;
        if      (c < 8)  v = emb_id    [idx_s[r][1] * 8  + c];
        else if (c < 16) v = emb_period[idx_s[r][0] * 8  + (c - 8)];
        else if (c < 32) v = emb_time  [idx_s[r][2] * 16 + (c - 16)];
        else if (c < 68) v = x[(row0 + r) * XCOLS + 3 + (c - 32)];
        sm[OFF_EMB + idx] = v;
    }
    CP_WAIT0();
    __syncthreads();   // Wf1 + emb ready

    float* H = sm + OFF_H;
    #define HBUF(gg, p) (H + (((gg) * 2 + (p)) * 8) * HID)

    float acc[8];

    // ---- f1: emb(72) -> H[g][0];  prefetch Wf2 -> W1 ----
    stage_async(Wf2, smb + OFF_W1 * 4, tid); CP_COMMIT();
    gemv8_acc<72, 72>(sm + OFF_EMB + g * 8 * 72, sm + OFF_W0, bf1[t], acc, t);
    #pragma unroll
    for (int r = 0; r < 8; r++) HBUF(g, 0)[r * HID + t] = fmaxf(acc[r], 0.f);
    CP_WAIT0();
    __syncthreads();

    // ---- f2: H[g][0] -> H[g][1];  prefetch Wc1 -> W0 ----
    stage_async(Wc1, smb + OFF_W0 * 4, tid); CP_COMMIT();
    gemv8_acc<128, 128>(HBUF(g, 0), sm + OFF_W1, bf2[t], acc, t);
    #pragma unroll
    for (int r = 0; r < 8; r++) HBUF(g, 1)[r * HID + t] = fmaxf(acc[r], 0.f);
    CP_WAIT0();
    __syncthreads();

    // ---- c1: H[g][1] -> H[g][0] (hc);  prefetch Wb1 -> W1 ----
    stage_async(Wb1, smb + OFF_W1 * 4, tid); CP_COMMIT();
    gemv8_acc<128, 128>(HBUF(g, 1), sm + OFF_W0, bc1[t], acc, t);
    #pragma unroll
    for (int r = 0; r < 8; r++) HBUF(g, 0)[r * HID + t] = fmaxf(acc[r], 0.f);
    CP_WAIT0();
    __syncthreads();

    // ---- b1: H[g][1] -> hb (registers only) ----
    gemv8_acc<128, 128>(HBUF(g, 1), sm + OFF_W1, bb1[t], acc, t);

    // sbase partials via warp shuffle: thread t holds hb[r][t]
    {
        float vb = Wb2[t];
        int lane = t & 31, warp_in_g = t >> 5;
        #pragma unroll
        for (int r = 0; r < 8; r++) {
            float p = fmaxf(acc[r], 0.f) * vb;
            p += __shfl_xor_sync(0xffffffff, p, 16);
            p += __shfl_xor_sync(0xffffffff, p, 8);
            p += __shfl_xor_sync(0xffffffff, p, 4);
            p += __shfl_xor_sync(0xffffffff, p, 2);
            p += __shfl_xor_sync(0xffffffff, p, 1);
            if (lane == 0) sm[OFF_RED + (g * 8 + r) * 4 + warp_in_g] = p;
        }
    }
    __syncthreads();

    // ---- epilogue dots: cbar[16][6], sbase[16] ----
    {
        int rb = tid >> 4, slot = tid & 15;
        int gg = rb >> 3, rr = rb & 7;
        if (slot < 6) {
            const float* hc = HBUF(gg, 0) + rr * HID;
            float s = 0.f;
            for (int i = 0; i < HID; i++) s += hc[i] * sm[OFF_WC2 + i * 8 + slot];
            float bb = 0.f;
            #pragma unroll
            for (int j = 0; j < 8; j++) bb += bc2[j * 6 + slot];
            sm[OFF_CBAR + rb * 8 + slot] = s + bb * 0.125f;
        } else if (slot == 6) {
            float s = sm[OFF_RED + rb * 4 + 0] + sm[OFF_RED + rb * 4 + 1]
                    + sm[OFF_RED + rb * 4 + 2] + sm[OFF_RED + rb * 4 + 3];
            sm[OFF_SB + rb] = s + bb2[0];
        }
    }
    __syncthreads();

    // ---- per-row piecewise cubic in X: 3 segments x (B0..B3) ----
    if (tid < 48) {
        int rb = tid / 3, m = tid - rb * 3;
        const float* c = sm + OFF_CBAR + rb * 8 + m;
        float c0 = c[0], c1 = c[1], c2 = c[2], c3 = c[3];
        const float k6 = 1.f / 6.f;
        float A0 = (c0 + 4.f * c1 + c2) * k6;
        float A1 = (c2 - c0) * 0.5f;
        float A2 = (c0 - 2.f * c1 + c2) * 0.5f;
        float A3 = (c3 - c0 + 3.f * (c1 - c2)) * k6;
        float d  = 1.5f - (float)m;           // u = 1.5*X + d
        float B0 = A0 + d * (A1 + d * (A2 + d * A3));
        float B1 = 1.5f * (A1 + d * (2.f * A2 + 3.f * A3 * d));
        float B2 = 2.25f * (A2 + 3.f * A3 * d);
        float B3 = 3.375f * A3;
        ((float4*)(sm + OFF_CB))[rb * 4 + m] = make_float4(B0, B1, B2, B3);
    }
    __syncthreads();

    // ---- budget phase: 16 rows x 512 points = 2048 float4 ----
    // silu(x) for x in [-1,1]: sigma(x) = 0.5 + x*P(x^2), degree-4 Horner, no MUFU
    const float4* bud4 = (const float4*)budget + row0 * 128;
    float4* out4 = (float4*)out + row0 * 128;
    const float4* cb4 = (const float4*)(sm + OFF_CB);
    #pragma unroll
    for (int it = 0; it < 8; it++) {
        int q = tid + it * 256;
        int row = q >> 7;
        float4 bv = bud4[q];
        float sb = sm[OFF_SB + row];
        float xs[4] = {bv.x, bv.y, bv.z, bv.w};
        float o[4];
        #pragma unroll
        for (int e = 0; e < 4; e++) {
            float X = xs[e];
            float tp = fmaf(X, 1.5f, 1.5f);
            int m = min((int)tp, 2);
            float4 B = cb4[row * 4 + m];
            float sp = fmaf(fmaf(fmaf(B.w, X, B.z), X, B.y), X, B.x);
            float u = X * X;
            float P = fmaf(u, fmaf(u, fmaf(u, fmaf(u, 2.1357286e-5f, -2.1081349e-4f),
                                           2.0833333e-3f), -2.0833333e-2f), 0.25f);
            float sil = X * fmaf(X, P, 0.5f);
            o[e] = sb * (sil + sp);
        }
        out4[q] = make_float4(o[0], o[1], o[2], o[3]);
    }
}

extern "C" void kernel_launch(void* const* d_in, const int* in_sizes, int n_in,
                              void* d_out, int out_size)
{
    const float* x          = (const float*)d_in[0];
    const float* budget     = (const float*)d_in[1];
    const float* emb_id     = (const float*)d_in[2];
    const float* emb_period = (const float*)d_in[3];
    const float* emb_time   = (const float*)d_in[4];
    const float* Wf1 = (const float*)d_in[5];
    const float* bf1 = (const float*)d_in[6];
    const float* Wf2 = (const float*)d_in[7];
    const float* bf2 = (const float*)d_in[8];
    const float* Wc1 = (const float*)d_in[9];
    const float* bc1 = (const float*)d_in[10];
    const float* Wc2 = (const float*)d_in[11];
    const float* bc2 = (const float*)d_in[12];
    // d_in[13..16] = Ws1/bs1/Ws2/bs2 : unused in reference output
    const float* Wb1 = (const float*)d_in[17];
    const float* bb1 = (const float*)d_in[18];
    const float* Wb2 = (const float*)d_in[19];
    const float* bb2 = (const float*)d_in[20];

    cudaFuncSetAttribute(fused_kernel, cudaFuncAttributeMaxDynamicSharedMemorySize, SMEM_BYTES);

    fused_kernel<<<BATCH / RPB, 256, SMEM_BYTES>>>(
        x, budget, emb_id, emb_period, emb_time,
        Wf1, bf1, Wf2, bf2, Wc1, bc1, Wc2, bc2,
        Wb1, bb1, Wb2, bb2, (float*)d_out);
}